// round 16
// baseline (speedup 1.0000x reference)
#include <cuda_runtime.h>
#include <math.h>

#define B_ 16
#define L_ 1024
#define CH 512
#define NCH 8192        // B_*CH
#define TPB 256
#define NSEG 48         // 3 scales * 16 batches
#define TOTL 1792       // 1024+512+256

#define IDX(i) ((i) + ((i) >> 5))   // smem pad: conflict-free FFT strides (4-byte words)
#define ZSTR 1056                    // buffer stride: IDX(1023)+2

// ---------------- static scratch ----------------
__device__ float     g_qT[(size_t)NCH*L_];
__device__ float     g_kT[(size_t)NCH*L_];
__device__ float     g_vT[(size_t)NCH*L_];
__device__ float     g_v2[(size_t)NCH*(L_/2)];    // 2x pooled v, channel-major
__device__ float     g_v4[(size_t)NCH*(L_/4)];    // 4x pooled v, channel-major
__device__ float     g_corr[(size_t)NCH*TOTL];
__device__ float     g_wv[(size_t)NCH*TOTL];      // weighted softmax*v rows (pre-interp)
__device__ unsigned  g_pkeys[(size_t)NCH*TOTL];
__device__ float2    g_twid[896];
__device__ float     g_cmp[(size_t)8*B_*TOTL];    // cm channel-partials
__device__ long long g_sumll[NSEG];
__device__ long long g_sqll[NSEG];
__device__ int       g_kvals[NSEG];
__device__ int       g_krem[NSEG];
__device__ unsigned  g_prefix[NSEG];
__device__ float     g_thresh[NSEG];
__device__ int       g_pcount[NSEG];
__device__ unsigned  g_h4k[(size_t)NSEG*4096];    // zero-init; self-cleaned every pass
__device__ unsigned  g_done0[NSEG];               // ticket counters; self-reset
__device__ unsigned  g_done1[NSEG];
__device__ unsigned  g_done2[NSEG];

__constant__ int    cLs[3]    = {1024, 512, 256};
__constant__ int    cCmSeg[3] = {0, 16384, 24576};

#define SCST 268435456.0      // 2^28 batch-stat fixed point (no int64 overflow)

__device__ __forceinline__ size_t corrOff(int s) {
    return s == 0 ? 0 : (s == 1 ? (size_t)NCH*1024 : (size_t)NCH*1536);
}
__device__ __forceinline__ unsigned f2k(float f) {
    unsigned u = __float_as_uint(f);
    return (u & 0x80000000u) ? ~u : (u | 0x80000000u);
}
__device__ __forceinline__ float k2f(unsigned k) {
    unsigned u = (k & 0x80000000u) ? (k & 0x7fffffffu) : ~k;
    return __uint_as_float(u);
}

// ---------------- init ----------------
__global__ void init_kernel() {
    int i = blockIdx.x * blockDim.x + threadIdx.x;
    int stride = gridDim.x * blockDim.x;
    if (i < NSEG) { g_sumll[i] = 0LL; g_sqll[i] = 0LL; g_pcount[i] = 0; }
    for (int j = i; j < 896; j += stride) {
        int N, jj;
        if (j < 512)      { N = 1024; jj = j; }
        else if (j < 768) { N = 512;  jj = j - 512; }
        else              { N = 256;  jj = j - 768; }
        double a = -6.283185307179586476925286766559 * (double)jj / (double)N;
        double sv, cv; sincos(a, &sv, &cv);
        g_twid[j] = make_float2((float)cv, (float)sv);
    }
}

// ---------------- transpose [B,L,CH] -> [B,CH,L] (+ pooled v) ----------------
__global__ void transpose3_kernel(const float* __restrict__ q,
                                  const float* __restrict__ k,
                                  const float* __restrict__ v) {
    __shared__ float tile[32][33];
    int b   = blockIdx.z;
    int ch0 = blockIdx.x * 32;
    int l0  = blockIdx.y * 32;
    const float* ins[3] = {q, k, v};
    float* outs[3] = {g_qT, g_kT, g_vT};
    int tx = threadIdx.x, ty = threadIdx.y;
    #pragma unroll
    for (int m = 0; m < 3; m++) {
        const float* in = ins[m];
        float* out = outs[m];
        for (int r = ty; r < 32; r += 8)
            tile[r][tx] = in[((size_t)b * L_ + (l0 + r)) * CH + ch0 + tx];
        __syncthreads();
        for (int r = ty; r < 32; r += 8)
            out[((size_t)b * CH + (ch0 + r)) * L_ + l0 + tx] = tile[tx][r];
        if (m == 2) {
            // pooled v rows: tile[lLocal][chLocal]
            for (int r = ty; r < 32; r += 8) {
                size_t ch = (size_t)b * CH + ch0 + r;
                if (tx < 16)
                    g_v2[ch * (L_/2) + (l0 >> 1) + tx] =
                        0.5f * (tile[2*tx][r] + tile[2*tx+1][r]);
                if (tx < 8)
                    g_v4[ch * (L_/4) + (l0 >> 2) + tx] =
                        0.25f * (tile[4*tx][r] + tile[4*tx+1][r] + tile[4*tx+2][r] + tile[4*tx+3][r]);
            }
        }
        __syncthreads();
    }
}

// ---------------- radix-4 FFT on smem (split re/im), twiddles from shared table ----------------
__device__ __forceinline__ void fft_pairs(float* sr, float* si, int N, int logN,
                                          const float2* tws, bool inv, int tid) {
    int st = 1;
    if (logN & 1) {
        for (int j = tid; j < (N >> 1); j += TPB) {
            int i0 = IDX(j << 1), i1 = IDX((j << 1) + 1);
            float ur = sr[i0], ui = si[i0], vr = sr[i1], vi = si[i1];
            sr[i0] = ur + vr; si[i0] = ui + vi;
            sr[i1] = ur - vr; si[i1] = ui - vi;
        }
        __syncthreads();
        st = 2;
    }
    int groups = N >> 2;
    for (; st < logN; st += 2) {
        int half = 1 << (st - 1);
        for (int g = tid; g < groups; g += TPB) {
            int pos = g & (half - 1);
            int blk = g >> (st - 1);
            int a0 = (blk << (st + 1)) + pos;
            int i0 = IDX(a0), i1 = IDX(a0 + half), i2 = IDX(a0 + 2*half), i3 = IDX(a0 + 3*half);
            float2 w  = tws[pos << (9 - st)];
            float2 w2 = tws[pos << (10 - st)];
            float wbr = w.x,  wbi = inv ? -w.y  : w.y;
            float war = w2.x, wai = inv ? -w2.y : w2.y;
            float a0r = sr[i0], a0i = si[i0], a1r = sr[i1], a1i = si[i1];
            float a2r = sr[i2], a2i = si[i2], a3r = sr[i3], a3i = si[i3];
            float t1r = war*a1r - wai*a1i, t1i = war*a1i + wai*a1r;
            float b0r = a0r + t1r, b0i = a0i + t1i;
            float b1r = a0r - t1r, b1i = a0i - t1i;
            float t3r = war*a3r - wai*a3i, t3i = war*a3i + wai*a3r;
            float b2r = a2r + t3r, b2i = a2i + t3i;
            float b3r = a2r - t3r, b3i = a2i - t3i;
            float u2r = wbr*b2r - wbi*b2i, u2i = wbr*b2i + wbi*b2r;
            float u3r = wbr*b3r - wbi*b3i, u3i = wbr*b3i + wbi*b3r;
            float vr3, vi3;
            if (!inv) { vr3 =  u3i; vi3 = -u3r; }
            else      { vr3 = -u3i; vi3 =  u3r; }
            sr[i0] = b0r + u2r; si[i0] = b0i + u2i;
            sr[i2] = b0r - u2r; si[i2] = b0i - u2i;
            sr[i1] = b1r + vr3; si[i1] = b1i + vi3;
            sr[i3] = b1r - vr3; si[i3] = b1i - vi3;
        }
        __syncthreads();
    }
}

// Fused Hermitian split + real-IFFT fold (R11 derivation).
__device__ __forceinline__ void hermY(const float* zr, const float* zi,
                                      float* wr, float* wi, int N, int logM,
                                      int twShift, const float2* tws, int tid) {
    int M = N >> 1;
    int shvM = 32 - logM;
    for (int f = tid; f <= (M >> 1); f += TPB) {
        int g = (N - f) & (N - 1);
        float a = zr[IDX(f)], b = zi[IDX(f)];
        float c = zr[IDX(g)], d = zi[IDX(g)];
        float qr = 0.5f*(a + c), qi = 0.5f*(b - d);
        float kr = 0.5f*(b + d), ki = 0.5f*(a - c);
        float Sfr = qr*kr - qi*ki, Sfi = qr*ki + qi*kr;
        int f2 = f + M;
        int g2 = (N - f2) & (N - 1);
        float a2 = zr[IDX(f2)], b2 = zi[IDX(f2)];
        float c2 = zr[IDX(g2)], d2 = zi[IDX(g2)];
        float q2r = 0.5f*(a2 + c2), q2i = 0.5f*(b2 - d2);
        float k2r = 0.5f*(b2 + d2), k2i = 0.5f*(a2 - c2);
        float S2r = q2r*k2r - q2i*k2i, S2i = q2r*k2i + q2i*k2r;

        float2 t = tws[f << twShift];
        float er = t.x, ei = -t.y;          // conj(tw_N[f])
        float Er = Sfr + S2r, Ei = Sfi + S2i;
        float Dr = Sfr - S2r, Di = Sfi - S2i;
        float Or = Dr*er - Di*ei, Oi = Dr*ei + Di*er;

        int pf = IDX((int)(__brev((unsigned)f) >> shvM));
        wr[pf] = Er - Oi; wi[pf] = Ei + Or;
        if (f != 0 && f != (M >> 1)) {
            int m2 = M - f;
            int pm = IDX((int)(__brev((unsigned)m2) >> shvM));
            wr[pm] = Er + Oi; wi[pm] = Or - Ei;
        }
    }
}

__device__ __forceinline__ void derive_half(float* zr, float* zi, int Lout, int shiftTw,
                                            const float2* tws, int tid) {
    for (int f = tid; f < Lout; f += TPB) {
        float2 t = tws[f << shiftTw];
        float er = t.x, ei = -t.y;
        float ar = zr[IDX(f)],        ai = zi[IDX(f)];
        float br = zr[IDX(f + Lout)], bi = zi[IDX(f + Lout)];
        float p1r = ar * (1.0f + er) - ai * ei;
        float p1i = ai * (1.0f + er) + ar * ei;
        float p2r = br * (1.0f - er) + bi * ei;
        float p2i = bi * (1.0f - er) - br * ei;
        zr[IDX(f)] = 0.25f * (p1r + p2r);
        zi[IDX(f)] = 0.25f * (p1i + p2i);
    }
}

// interleaved corr value: corr[t] (unnormalized) lives in wr/wi half-size buffers
__device__ __forceinline__ float cval(const float* wr, const float* wi, int t) {
    int m = t >> 1;
    return (t & 1) ? wi[IDX(m)] : wr[IDX(m)];
}

// Per-scale epilogue: corr write + stats + two-pass peak emission
// (block-local shared counter; ONE global base atomic per block per scale).
__device__ void epilogue(int sIdx, int ch, int b, int seg, int Ls,
                         const float* wr, const float* wi,
                         int tid, double* wsum, double* wsq, int* s_cnt, int* s_base) {
    const float invN = 1.0f / (float)Ls;
    int lane = tid & 31;
    float* outRow = g_corr + corrOff(sIdx) + (size_t)ch * Ls;
    double sm = 0.0, sq = 0.0;
    int nv = Ls >> 2;
    if (tid == 0) *s_cnt = 0;
    if (tid < nv) {
        int m0 = 2 * tid;
        float v0 = wr[IDX(m0)]   * invN, v1 = wi[IDX(m0)]   * invN;
        float v2 = wr[IDX(m0+1)] * invN, v3 = wi[IDX(m0+1)] * invN;
        ((float4*)outRow)[tid] = make_float4(v0, v1, v2, v3);
        sm = (double)v0 + (double)v1 + (double)v2 + (double)v3;
        sq = (double)v0*v0 + (double)v1*v1 + (double)v2*v2 + (double)v3*v3;
    }
    #pragma unroll
    for (int off = 16; off > 0; off >>= 1) {
        sm += __shfl_down_sync(0xffffffffu, sm, off);
        sq += __shfl_down_sync(0xffffffffu, sq, off);
    }
    if (lane == 0) { wsum[tid >> 5] = sm; wsq[tid >> 5] = sq; }
    __syncthreads();
    if (tid == 0) {
        double ts = 0.0, tq = 0.0;
        #pragma unroll
        for (int w = 0; w < 8; w++) { ts += wsum[w]; tq += wsq[w]; }
        atomicAdd((unsigned long long*)&g_sumll[seg], (unsigned long long)__double2ll_rn(ts * SCST));
        atomicAdd((unsigned long long*)&g_sqll[seg],  (unsigned long long)__double2ll_rn(tq * SCST));
    }

    // pass 1: peak count
    int loc = 0;
    for (int t = tid + 1; t < Ls - 1; t += TPB) {
        float v = cval(wr, wi, t);
        if (v > cval(wr, wi, t-1) && v > cval(wr, wi, t+1)) loc++;
    }
    if (loc) atomicAdd(s_cnt, loc);
    __syncthreads();
    if (tid == 0) { *s_base = atomicAdd(&g_pcount[seg], *s_cnt); *s_cnt = 0; }
    __syncthreads();
    // pass 2: ballot-aggregated writes via shared counter
    unsigned* keys = g_pkeys + corrOff(sIdx) + (size_t)b * CH * Ls;
    int iters = Ls / TPB;
    for (int it = 0; it < iters; it++) {
        int t = it * TPB + tid + 1;
        bool pk = false; float v = 0.0f;
        if (t < Ls - 1) {
            v = cval(wr, wi, t);
            pk = (v > cval(wr, wi, t-1) && v > cval(wr, wi, t+1));
        }
        unsigned mask = __ballot_sync(0xffffffffu, pk);
        if (mask) {
            int leader = __ffs(mask) - 1;
            int wb = 0;
            if (lane == leader) wb = atomicAdd(s_cnt, __popc(mask));
            wb = __shfl_sync(0xffffffffu, wb, leader);
            if (pk) {
                int rank = __popc(mask & ((1u << lane) - 1u));
                keys[*s_base + wb + rank] = f2k(v * invN);
            }
        }
    }
    __syncthreads();
}

// ---------------- fused corr: 1 fwd 1024 FFT + spectral pooling + 3 half-size inverse FFTs ----------------
__global__ void corr_fused_kernel() {
    extern __shared__ float smem[];
    __shared__ double wsum[8], wsq[8];
    __shared__ int s_cnt, s_base;
    int ch = blockIdx.x;
    int b  = ch >> 9;
    float* zr = smem;
    float* zi = smem + ZSTR;
    float* wr = smem + 2 * ZSTR;
    float* wi = smem + 3 * ZSTR;
    float2* tws = (float2*)(smem + 4 * ZSTR);   // 512 entries, 4 KB
    int tid = threadIdx.x;

    {
        float4 t = ((const float4*)g_twid)[tid];
        ((float4*)tws)[tid] = t;
    }
    {
        float4 qa = ((const float4*)(g_qT + (size_t)ch * L_))[tid];
        float4 ka = ((const float4*)(g_kT + (size_t)ch * L_))[tid];
        int t0 = tid * 4;
        int r0 = IDX((int)(__brev((unsigned)(t0  )) >> 22));
        int r1 = IDX((int)(__brev((unsigned)(t0+1)) >> 22));
        int r2 = IDX((int)(__brev((unsigned)(t0+2)) >> 22));
        int r3 = IDX((int)(__brev((unsigned)(t0+3)) >> 22));
        zr[r0] = qa.x; zi[r0] = ka.x;
        zr[r1] = qa.y; zi[r1] = ka.y;
        zr[r2] = qa.z; zi[r2] = ka.z;
        zr[r3] = qa.w; zi[r3] = ka.w;
    }
    __syncthreads();

    fft_pairs(zr, zi, 1024, 10, tws, false, tid);   // packed forward FFT, natural order

    // scale 0: N=1024 -> 512-pt IFFT
    hermY(zr, zi, wr, wi, 1024, 9, 0, tws, tid);
    __syncthreads();
    fft_pairs(wr, wi, 512, 9, tws, true, tid);
    epilogue(0, ch, b, b, 1024, wr, wi, tid, wsum, wsq, &s_cnt, &s_base);

    // scale 1
    derive_half(zr, zi, 512, 0, tws, tid);
    __syncthreads();
    hermY(zr, zi, wr, wi, 512, 8, 1, tws, tid);
    __syncthreads();
    fft_pairs(wr, wi, 256, 8, tws, true, tid);
    epilogue(1, ch, b, 16 + b, 512, wr, wi, tid, wsum, wsq, &s_cnt, &s_base);

    // scale 2
    derive_half(zr, zi, 256, 1, tws, tid);
    __syncthreads();
    hermY(zr, zi, wr, wi, 256, 7, 2, tws, tid);
    __syncthreads();
    fft_pairs(wr, wi, 128, 7, tws, true, tid);
    epilogue(2, ch, b, 32 + b, 256, wr, wi, tid, wsum, wsq, &s_cnt, &s_base);
}

// ---------------- cm: 8-way channel-partial sums (combine folded into histscan pass 0) ----------------
__global__ void cm_part_kernel() {
    int idx = blockIdx.x * blockDim.x + threadIdx.x;
    if (idx >= 8 * B_ * TOTL) return;
    int i    = idx % (B_ * TOTL);
    int part = idx / (B_ * TOTL);
    int sIdx, b, t, Ls;
    if (i < 16384)      { sIdx = 0; Ls = 1024; int j = i;         b = j >> 10; t = j & 1023; }
    else if (i < 24576) { sIdx = 1; Ls = 512;  int j = i - 16384; b = j >> 9;  t = j & 511;  }
    else                { sIdx = 2; Ls = 256;  int j = i - 24576; b = j >> 8;  t = j & 255;  }
    const float* base = g_corr + corrOff(sIdx) + (size_t)(b * CH + part * 64) * Ls + t;
    float a0 = 0.f, a1 = 0.f, a2 = 0.f, a3 = 0.f;
    #pragma unroll 4
    for (int ch = 0; ch < 64; ch += 4) {
        a0 += base[(size_t)ch * Ls];
        a1 += base[(size_t)(ch + 1) * Ls];
        a2 += base[(size_t)(ch + 2) * Ls];
        a3 += base[(size_t)(ch + 3) * Ls];
    }
    g_cmp[idx] = (a0 + a1) + (a2 + a3);
}

// ---------------- fused hist+scan: pass 0 (12b, + cm combine + MLP), pass 1 (12b), pass 2 (8b) ----------------
__global__ void histscan_kernel(int pass,
        const float* __restrict__ w1, const float* __restrict__ b1,
        const float* __restrict__ w2, const float* __restrict__ b2,
        const float* __restrict__ w3, const float* __restrict__ b3) {
    __shared__ unsigned hl[4096];
    __shared__ float cmrow[1024];
    __shared__ unsigned sscan[TPB];
    __shared__ int s_last, s_k;
    __shared__ int s_pkred[8];
    int seg = blockIdx.y;
    int sIdx = seg >> 4, b = seg & 15;
    int Ls = cLs[sIdx];
    int tid = threadIdx.x;
    int lane = tid & 31;
    unsigned* gh = g_h4k + (size_t)seg * 4096;
    unsigned* ctr = (pass == 0 ? g_done0 : (pass == 1 ? g_done1 : g_done2)) + seg;

    for (int i = tid; i < 4096; i += TPB) hl[i] = 0;
    __syncthreads();

    int cnt = g_pcount[seg];
    unsigned pref = (pass == 0) ? 0u : g_prefix[seg];
    const unsigned* keys = g_pkeys + corrOff(sIdx) + (size_t)b * CH * Ls;
    int stride = gridDim.x * TPB;
    int iters = (cnt + stride - 1) / stride;
    int i = blockIdx.x * TPB + tid;
    for (int it = 0; it < iters; it++, i += stride) {
        bool valid = (i < cnt);
        unsigned key = valid ? keys[i] : 0u;
        bool ok; unsigned bin;
        if (pass == 0)      { ok = valid;                                    bin = key >> 20; }
        else if (pass == 1) { ok = valid && ((key >> 20) == (pref >> 20));   bin = (key >> 8) & 0xfffu; }
        else                { ok = valid && ((key >> 8) == (pref >> 8));     bin = key & 0xffu; }
        unsigned tag = ok ? bin : 0xffffffffu;
        unsigned mm = __match_any_sync(0xffffffffu, tag);
        if (ok && lane == (__ffs(mm) - 1))
            atomicAdd(&hl[bin], (unsigned)__popc(mm));
    }
    __syncthreads();
    for (int j = tid; j < 4096; j += TPB)
        if (hl[j]) atomicAdd(&gh[j], hl[j]);
    __threadfence();
    if (tid == 0) {
        unsigned t = atomicAdd(ctr, 1u);
        s_last = (t == gridDim.x - 1) ? 1 : 0;
    }
    __syncthreads();
    if (!s_last) return;
    __threadfence();

    if (pass == 0) {
        // combine cm partials into shared row, then pk count + MLP -> k
        int cmIdx = cCmSeg[sIdx] + b * Ls;
        for (int t = tid; t < Ls; t += TPB) {
            float s = 0.0f;
            #pragma unroll
            for (int p = 0; p < 8; p++) s += g_cmp[(size_t)p * (B_ * TOTL) + cmIdx + t];
            cmrow[t] = s;
        }
        __syncthreads();
        int pcnt = 0;
        for (int t = tid + 1; t < Ls - 1; t += TPB) {
            float v = cmrow[t];
            if (v > cmrow[t - 1] && v > cmrow[t + 1]) pcnt++;
        }
        #pragma unroll
        for (int off = 16; off > 0; off >>= 1) pcnt += __shfl_down_sync(0xffffffffu, pcnt, off);
        if (lane == 0) s_pkred[tid >> 5] = pcnt;
        __syncthreads();
        if (tid == 0) {
            int pkc = 0;
            #pragma unroll
            for (int w = 0; w < 8; w++) pkc += s_pkred[w];
            const double invSC = 1.0 / SCST;
            float f2 = (float)pkc;
            long long tot = 0;
            for (int ii = 0; ii < B_; ii++) tot += g_sqll[sIdx * 16 + ii];
            float f0 = (float)((double)tot * invSC / ((double)B_ * (double)Ls));
            double n = (double)CH * (double)Ls;
            double s1 = (double)g_sumll[seg] * invSC;
            double s2 = (double)g_sqll[seg] * invSC;
            double mean = s1 / n;
            float f1 = (float)((s2 - mean * s1) / (n - 1.0));
            float h1[32];
            for (int j = 0; j < 32; j++) {
                float a = w1[j*3] * f0 + w1[j*3+1] * f1 + w1[j*3+2] * f2 + b1[j];
                h1[j] = a > 0.0f ? a : 0.0f;
            }
            float h2[16];
            for (int j = 0; j < 16; j++) {
                float a = b2[j];
                for (int i2 = 0; i2 < 32; i2++) a += w2[j*32+i2] * h1[i2];
                h2[j] = a > 0.0f ? a : 0.0f;
            }
            float a = b3[0];
            for (int i2 = 0; i2 < 16; i2++) a += w3[i2] * h2[i2];
            float ratio = 1.0f / (1.0f + expf(-a));
            int kv = (int)(ratio * (float)Ls);
            if (kv < 1) kv = 1;
            if (kv > Ls) kv = Ls;
            g_kvals[seg] = kv;
            s_k = kv;
        }
    } else {
        if (tid == 0) s_k = g_krem[seg];
    }
    __syncthreads();
    unsigned k = (unsigned)s_k;

    int nb = (pass == 2) ? 256 : 4096;
    int bpt = nb / TPB;
    int cstart = tid * bpt;
    unsigned myChunk = 0;
    for (int j = 0; j < bpt; j++) myChunk += gh[cstart + j];
    sscan[tid] = myChunk;
    __syncthreads();
    for (int off = 1; off < TPB; off <<= 1) {
        unsigned v = (tid + off < TPB) ? sscan[tid + off] : 0u;
        __syncthreads();
        sscan[tid] += v;
        __syncthreads();
    }
    unsigned incl = sscan[tid];
    unsigned cumBefore = incl - myChunk;
    if (myChunk > 0 && cumBefore < k && incl >= k) {
        unsigned cum = cumBefore;
        for (int bin = cstart + bpt - 1; bin >= cstart; --bin) {
            unsigned h = gh[bin];
            if (cum + h >= k) {
                if (pass == 0) {
                    g_prefix[seg] = (unsigned)bin << 20;
                    g_krem[seg] = (int)(k - cum);
                } else if (pass == 1) {
                    g_prefix[seg] = (pref & 0xfff00000u) | ((unsigned)bin << 8);
                    g_krem[seg] = (int)(k - cum);
                } else {
                    g_thresh[seg] = k2f((pref & 0xffffff00u) | (unsigned)bin);
                }
                break;
            }
            cum += h;
        }
    }
    __syncthreads();
    for (int j = tid; j < 4096; j += TPB) gh[j] = 0u;
    if (tid == 0) *ctr = 0u;
}

// ---------------- final: masked softmax * pooled v (pre-interp rows), shuffle reductions ----------------
__global__ void final_all_kernel(const float* __restrict__ swarr) {
    extern __shared__ float smem[];
    __shared__ float red8[8];
    __shared__ float s_m, s_inv;
    int sIdx = blockIdx.x >> 13;
    int ch   = blockIdx.x & (NCH - 1);
    int b    = ch >> 9;
    int seg  = sIdx * 16 + b;
    int Ls = cLs[sIdx];
    int tid = threadIdx.x;
    int lane = tid & 31, wid = tid >> 5;
    float* sc = smem;
    float* so = smem + Ls;

    const float4* c4 = (const float4*)(g_corr + corrOff(sIdx) + (size_t)ch * Ls);
    int nv = Ls >> 2;
    if (tid < nv) ((float4*)sc)[tid] = c4[tid];
    __syncthreads();

    float thr = g_thresh[seg];
    bool useAll = (g_pcount[seg] <= g_kvals[seg]);

    float m = 0.0f;
    for (int t = tid; t < Ls; t += TPB) {
        float a = 0.0f;
        if (t > 0 && t < Ls - 1) {
            float v = sc[t];
            if (v > sc[t - 1] && v > sc[t + 1] && (useAll || v >= thr)) a = v;
        }
        so[t] = a;
        m = fmaxf(m, a);
    }
    #pragma unroll
    for (int off = 16; off > 0; off >>= 1)
        m = fmaxf(m, __shfl_down_sync(0xffffffffu, m, off));
    if (lane == 0) red8[wid] = m;
    __syncthreads();
    if (tid == 0) {
        float mm = 0.0f;
        #pragma unroll
        for (int w = 0; w < 8; w++) mm = fmaxf(mm, red8[w]);
        s_m = mm;
    }
    __syncthreads();
    m = s_m;

    float ds = 0.0f;
    for (int t = tid; t < Ls; t += TPB) {
        float e = __expf(so[t] - m);
        so[t] = e;
        ds += e;
    }
    #pragma unroll
    for (int off = 16; off > 0; off >>= 1)
        ds += __shfl_down_sync(0xffffffffu, ds, off);
    if (lane == 0) red8[wid] = ds;
    __syncthreads();
    if (tid == 0) {
        float s = 0.0f;
        #pragma unroll
        for (int w = 0; w < 8; w++) s += red8[w];
        s_inv = 1.0f / s;
    }
    __syncthreads();
    float inv = s_inv;

    float sw = swarr[sIdx];
    float c = sw * inv;
    if (sIdx == 0) {
        float4 vv = ((const float4*)(g_vT + (size_t)ch * L_))[tid];
        int t0 = tid * 4;
        so[t0  ] = c * so[t0  ] * vv.x;
        so[t0+1] = c * so[t0+1] * vv.y;
        so[t0+2] = c * so[t0+2] * vv.z;
        so[t0+3] = c * so[t0+3] * vv.w;
    } else if (sIdx == 1) {
        float2 vv = ((const float2*)(g_v2 + (size_t)ch * (L_/2)))[tid];
        int t0 = tid * 2;
        so[t0  ] = c * so[t0  ] * vv.x;
        so[t0+1] = c * so[t0+1] * vv.y;
    } else {
        float vv = g_v4[(size_t)ch * (L_/4) + tid];
        so[tid] = c * so[tid] * vv;
    }
    __syncthreads();

    float* outRow = g_wv + corrOff(sIdx) + (size_t)ch * Ls;
    if (tid < nv) ((float4*)outRow)[tid] = ((const float4*)so)[tid];
}

// ---------------- untranspose + on-the-fly interpolation + sum 3 scales ----------------
__global__ void untranspose_kernel(float* __restrict__ out) {
    __shared__ float tile[32][33];
    int b   = blockIdx.z;
    int ch0 = blockIdx.x * 32;
    int l0  = blockIdx.y * 32;
    int tx = threadIdx.x, ty = threadIdx.y;
    int l = l0 + tx;

    float s1 = 0.5f * (float)l - 0.25f;  if (s1 < 0.0f) s1 = 0.0f;
    int x10 = (int)s1; int x11 = x10 + 1; if (x11 > 511) x11 = 511;
    float lam1 = s1 - (float)x10;
    float s2 = 0.25f * (float)l - 0.375f; if (s2 < 0.0f) s2 = 0.0f;
    int x20 = (int)s2; int x21 = x20 + 1; if (x21 > 255) x21 = 255;
    float lam2 = s2 - (float)x20;

    const float* w1base = g_wv + (size_t)NCH * 1024;
    const float* w2base = g_wv + (size_t)NCH * 1536;

    for (int r = ty; r < 32; r += 8) {
        size_t ch = (size_t)b * CH + ch0 + r;
        const float* w0 = g_wv + ch * 1024;
        const float* w1 = w1base + ch * 512;
        const float* w2 = w2base + ch * 256;
        float v = w0[l]
                + w1[x10] * (1.0f - lam1) + w1[x11] * lam1
                + w2[x20] * (1.0f - lam2) + w2[x21] * lam2;
        tile[r][tx] = v;
    }
    __syncthreads();
    for (int r = ty; r < 32; r += 8)
        out[((size_t)b * L_ + (l0 + r)) * CH + ch0 + tx] = tile[tx][r];
}

// ---------------- launch ----------------
extern "C" void kernel_launch(void* const* d_in, const int* in_sizes, int n_in,
                              void* d_out, int out_size) {
    (void)in_sizes; (void)n_in; (void)out_size;
    const float* q  = (const float*)d_in[0];
    const float* kk = (const float*)d_in[1];
    const float* v  = (const float*)d_in[2];
    const float* sw = (const float*)d_in[3];
    const float* w1 = (const float*)d_in[4];
    const float* b1 = (const float*)d_in[5];
    const float* w2 = (const float*)d_in[6];
    const float* b2 = (const float*)d_in[7];
    const float* w3 = (const float*)d_in[8];
    const float* b3 = (const float*)d_in[9];
    float* out = (float*)d_out;

    init_kernel<<<64, TPB>>>();

    dim3 tgrid(CH / 32, L_ / 32, B_);
    dim3 tblk(32, 8);
    transpose3_kernel<<<tgrid, tblk>>>(q, kk, v);

    int fftSmem = 4 * ZSTR * sizeof(float) + 512 * sizeof(float2);   // 20992 B
    corr_fused_kernel<<<NCH, TPB, fftSmem>>>();

    cm_part_kernel<<<(8 * B_ * TOTL + TPB - 1) / TPB, TPB>>>();

    dim3 hg(32, NSEG);
    histscan_kernel<<<hg, TPB>>>(0, w1, b1, w2, b2, w3, b3);
    histscan_kernel<<<hg, TPB>>>(1, w1, b1, w2, b2, w3, b3);
    histscan_kernel<<<hg, TPB>>>(2, w1, b1, w2, b2, w3, b3);

    final_all_kernel<<<3 * NCH, TPB, 2 * 1024 * sizeof(float)>>>(sw);

    untranspose_kernel<<<tgrid, tblk>>>(out);
}

// round 17
// speedup vs baseline: 1.0310x; 1.0310x over previous
#include <cuda_runtime.h>
#include <math.h>

#define B_ 16
#define L_ 1024
#define CH 512
#define NCH 8192        // B_*CH
#define TPB 256
#define NSEG 48         // 3 scales * 16 batches
#define TOTL 1792       // 1024+512+256

#define IDX(i) ((i) + ((i) >> 5))   // smem pad: conflict-free FFT strides (4-byte words)
#define ZSTR 1056                    // buffer stride: IDX(1023)+2

// ---------------- static scratch ----------------
__device__ float     g_qT[(size_t)NCH*L_];
__device__ float     g_kT[(size_t)NCH*L_];
__device__ float     g_vT[(size_t)NCH*L_];
__device__ float     g_corr[(size_t)NCH*TOTL];
__device__ float     g_wv[(size_t)NCH*TOTL];      // weighted softmax*v rows (pre-interp)
__device__ unsigned  g_pkeys[(size_t)NCH*TOTL];
__device__ float2    g_twid[896];
__device__ float     g_cmp[(size_t)8*B_*TOTL];    // cm channel-partials
__device__ float     g_cm[B_*TOTL];               // channel-sum rows
__device__ long long g_sumll[NSEG];
__device__ long long g_sqll[NSEG];
__device__ int       g_kvals[NSEG];
__device__ int       g_krem[NSEG];
__device__ unsigned  g_prefix[NSEG];
__device__ float     g_thresh[NSEG];
__device__ int       g_pcount[NSEG];
__device__ unsigned  g_h4k[(size_t)NSEG*4096];    // zero-init; self-cleaned every pass
__device__ unsigned  g_done0[NSEG];               // ticket counters; self-reset
__device__ unsigned  g_done1[NSEG];
__device__ unsigned  g_done2[NSEG];

__constant__ int    cLs[3]    = {1024, 512, 256};
__constant__ int    cCmSeg[3] = {0, 16384, 24576};

#define SCST 268435456.0      // 2^28 batch-stat fixed point (no int64 overflow)

__device__ __forceinline__ size_t corrOff(int s) {
    return s == 0 ? 0 : (s == 1 ? (size_t)NCH*1024 : (size_t)NCH*1536);
}
__device__ __forceinline__ unsigned f2k(float f) {
    unsigned u = __float_as_uint(f);
    return (u & 0x80000000u) ? ~u : (u | 0x80000000u);
}
__device__ __forceinline__ float k2f(unsigned k) {
    unsigned u = (k & 0x80000000u) ? (k & 0x7fffffffu) : ~k;
    return __uint_as_float(u);
}

// ---------------- init ----------------
__global__ void init_kernel() {
    int i = blockIdx.x * blockDim.x + threadIdx.x;
    int stride = gridDim.x * blockDim.x;
    if (i < NSEG) { g_sumll[i] = 0LL; g_sqll[i] = 0LL; g_pcount[i] = 0; }
    for (int j = i; j < 896; j += stride) {
        int N, jj;
        if (j < 512)      { N = 1024; jj = j; }
        else if (j < 768) { N = 512;  jj = j - 512; }
        else              { N = 256;  jj = j - 768; }
        double a = -6.283185307179586476925286766559 * (double)jj / (double)N;
        double sv, cv; sincos(a, &sv, &cv);
        g_twid[j] = make_float2((float)cv, (float)sv);
    }
}

// ---------------- transpose [B,L,CH] -> [B,CH,L] ----------------
__global__ void transpose3_kernel(const float* __restrict__ q,
                                  const float* __restrict__ k,
                                  const float* __restrict__ v) {
    __shared__ float tile[32][33];
    int b   = blockIdx.z;
    int ch0 = blockIdx.x * 32;
    int l0  = blockIdx.y * 32;
    const float* ins[3] = {q, k, v};
    float* outs[3] = {g_qT, g_kT, g_vT};
    int tx = threadIdx.x, ty = threadIdx.y;
    #pragma unroll
    for (int m = 0; m < 3; m++) {
        const float* in = ins[m];
        float* out = outs[m];
        for (int r = ty; r < 32; r += 8)
            tile[r][tx] = in[((size_t)b * L_ + (l0 + r)) * CH + ch0 + tx];
        __syncthreads();
        for (int r = ty; r < 32; r += 8)
            out[((size_t)b * CH + (ch0 + r)) * L_ + l0 + tx] = tile[tx][r];
        __syncthreads();
    }
}

// ---------------- radix-4 FFT on smem (split re/im), twiddles from shared table ----------------
__device__ __forceinline__ void fft_pairs(float* sr, float* si, int N, int logN,
                                          const float2* tws, bool inv, int tid) {
    int st = 1;
    if (logN & 1) {
        for (int j = tid; j < (N >> 1); j += TPB) {
            int i0 = IDX(j << 1), i1 = IDX((j << 1) + 1);
            float ur = sr[i0], ui = si[i0], vr = sr[i1], vi = si[i1];
            sr[i0] = ur + vr; si[i0] = ui + vi;
            sr[i1] = ur - vr; si[i1] = ui - vi;
        }
        __syncthreads();
        st = 2;
    }
    int groups = N >> 2;
    for (; st < logN; st += 2) {
        int half = 1 << (st - 1);
        for (int g = tid; g < groups; g += TPB) {
            int pos = g & (half - 1);
            int blk = g >> (st - 1);
            int a0 = (blk << (st + 1)) + pos;
            int i0 = IDX(a0), i1 = IDX(a0 + half), i2 = IDX(a0 + 2*half), i3 = IDX(a0 + 3*half);
            float2 w  = tws[pos << (9 - st)];
            float2 w2 = tws[pos << (10 - st)];
            float wbr = w.x,  wbi = inv ? -w.y  : w.y;
            float war = w2.x, wai = inv ? -w2.y : w2.y;
            float a0r = sr[i0], a0i = si[i0], a1r = sr[i1], a1i = si[i1];
            float a2r = sr[i2], a2i = si[i2], a3r = sr[i3], a3i = si[i3];
            float t1r = war*a1r - wai*a1i, t1i = war*a1i + wai*a1r;
            float b0r = a0r + t1r, b0i = a0i + t1i;
            float b1r = a0r - t1r, b1i = a0i - t1i;
            float t3r = war*a3r - wai*a3i, t3i = war*a3i + wai*a3r;
            float b2r = a2r + t3r, b2i = a2i + t3i;
            float b3r = a2r - t3r, b3i = a2i - t3i;
            float u2r = wbr*b2r - wbi*b2i, u2i = wbr*b2i + wbi*b2r;
            float u3r = wbr*b3r - wbi*b3i, u3i = wbr*b3i + wbi*b3r;
            float vr3, vi3;
            if (!inv) { vr3 =  u3i; vi3 = -u3r; }
            else      { vr3 = -u3i; vi3 =  u3r; }
            sr[i0] = b0r + u2r; si[i0] = b0i + u2i;
            sr[i2] = b0r - u2r; si[i2] = b0i - u2i;
            sr[i1] = b1r + vr3; si[i1] = b1i + vi3;
            sr[i3] = b1r - vr3; si[i3] = b1i - vi3;
        }
        __syncthreads();
    }
}

// Fused Hermitian split + real-IFFT fold (R11 derivation).
__device__ __forceinline__ void hermY(const float* zr, const float* zi,
                                      float* wr, float* wi, int N, int logM,
                                      int twShift, const float2* tws, int tid) {
    int M = N >> 1;
    int shvM = 32 - logM;
    for (int f = tid; f <= (M >> 1); f += TPB) {
        int g = (N - f) & (N - 1);
        float a = zr[IDX(f)], b = zi[IDX(f)];
        float c = zr[IDX(g)], d = zi[IDX(g)];
        float qr = 0.5f*(a + c), qi = 0.5f*(b - d);
        float kr = 0.5f*(b + d), ki = 0.5f*(a - c);
        float Sfr = qr*kr - qi*ki, Sfi = qr*ki + qi*kr;
        int f2 = f + M;
        int g2 = (N - f2) & (N - 1);
        float a2 = zr[IDX(f2)], b2 = zi[IDX(f2)];
        float c2 = zr[IDX(g2)], d2 = zi[IDX(g2)];
        float q2r = 0.5f*(a2 + c2), q2i = 0.5f*(b2 - d2);
        float k2r = 0.5f*(b2 + d2), k2i = 0.5f*(a2 - c2);
        float S2r = q2r*k2r - q2i*k2i, S2i = q2r*k2i + q2i*k2r;

        float2 t = tws[f << twShift];
        float er = t.x, ei = -t.y;          // conj(tw_N[f])
        float Er = Sfr + S2r, Ei = Sfi + S2i;
        float Dr = Sfr - S2r, Di = Sfi - S2i;
        float Or = Dr*er - Di*ei, Oi = Dr*ei + Di*er;

        int pf = IDX((int)(__brev((unsigned)f) >> shvM));
        wr[pf] = Er - Oi; wi[pf] = Ei + Or;
        if (f != 0 && f != (M >> 1)) {
            int m2 = M - f;
            int pm = IDX((int)(__brev((unsigned)m2) >> shvM));
            wr[pm] = Er + Oi; wi[pm] = Or - Ei;
        }
    }
}

__device__ __forceinline__ void derive_half(float* zr, float* zi, int Lout, int shiftTw,
                                            const float2* tws, int tid) {
    for (int f = tid; f < Lout; f += TPB) {
        float2 t = tws[f << shiftTw];
        float er = t.x, ei = -t.y;
        float ar = zr[IDX(f)],        ai = zi[IDX(f)];
        float br = zr[IDX(f + Lout)], bi = zi[IDX(f + Lout)];
        float p1r = ar * (1.0f + er) - ai * ei;
        float p1i = ai * (1.0f + er) + ar * ei;
        float p2r = br * (1.0f - er) + bi * ei;
        float p2i = bi * (1.0f - er) - br * ei;
        zr[IDX(f)] = 0.25f * (p1r + p2r);
        zi[IDX(f)] = 0.25f * (p1i + p2i);
    }
}

// Per-scale epilogue: corr write + stats + two-pass PAIR-BASED peak emission
// corr[2m] = wr[m], corr[2m+1] = wi[m] (unnormalized).
// Peak at 2m:   m>0   && wr[m] > wi[m-1] && wr[m] > wi[m]
// Peak at 2m+1: m<M-1 && wi[m] > wr[m]   && wi[m] > wr[m+1]
__device__ void epilogue(int sIdx, int ch, int b, int seg, int Ls,
                         const float* wr, const float* wi,
                         int tid, double* wsum, double* wsq, int* s_cnt, int* s_base) {
    const float invN = 1.0f / (float)Ls;
    int lane = tid & 31;
    float* outRow = g_corr + corrOff(sIdx) + (size_t)ch * Ls;
    double sm = 0.0, sq = 0.0;
    int nv = Ls >> 2;
    int M = Ls >> 1;
    if (tid == 0) *s_cnt = 0;
    if (tid < nv) {
        int m0 = 2 * tid;
        float v0 = wr[IDX(m0)]   * invN, v1 = wi[IDX(m0)]   * invN;
        float v2 = wr[IDX(m0+1)] * invN, v3 = wi[IDX(m0+1)] * invN;
        ((float4*)outRow)[tid] = make_float4(v0, v1, v2, v3);
        sm = (double)v0 + (double)v1 + (double)v2 + (double)v3;
        sq = (double)v0*v0 + (double)v1*v1 + (double)v2*v2 + (double)v3*v3;
    }
    #pragma unroll
    for (int off = 16; off > 0; off >>= 1) {
        sm += __shfl_down_sync(0xffffffffu, sm, off);
        sq += __shfl_down_sync(0xffffffffu, sq, off);
    }
    if (lane == 0) { wsum[tid >> 5] = sm; wsq[tid >> 5] = sq; }
    __syncthreads();
    if (tid == 0) {
        double ts = 0.0, tq = 0.0;
        #pragma unroll
        for (int w = 0; w < 8; w++) { ts += wsum[w]; tq += wsq[w]; }
        atomicAdd((unsigned long long*)&g_sumll[seg], (unsigned long long)__double2ll_rn(ts * SCST));
        atomicAdd((unsigned long long*)&g_sqll[seg],  (unsigned long long)__double2ll_rn(tq * SCST));
    }

    // pass 1: peak count (pair-based)
    int loc = 0;
    for (int m = tid; m < M; m += TPB) {
        float e0 = wr[IDX(m)], o0 = wi[IDX(m)];
        if (m > 0     && e0 > wi[IDX(m-1)] && e0 > o0)          loc++;
        if (m < M - 1 && o0 > e0           && o0 > wr[IDX(m+1)]) loc++;
    }
    if (loc) atomicAdd(s_cnt, loc);
    __syncthreads();
    if (tid == 0) { *s_base = atomicAdd(&g_pcount[seg], *s_cnt); *s_cnt = 0; }
    __syncthreads();
    // pass 2: ballot-aggregated writes via shared counter (pair-based)
    unsigned* keys = g_pkeys + corrOff(sIdx) + (size_t)b * CH * Ls;
    int iters = M / TPB;
    if (iters == 0) iters = 1;
    for (int it = 0; it < iters; it++) {
        int m = it * TPB + tid;
        bool pk0 = false, pk1 = false;
        float e0 = 0.0f, o0 = 0.0f;
        if (m < M) {
            e0 = wr[IDX(m)]; o0 = wi[IDX(m)];
            if (m > 0     && e0 > wi[IDX(m-1)] && e0 > o0)          pk0 = true;
            if (m < M - 1 && o0 > e0           && o0 > wr[IDX(m+1)]) pk1 = true;
        }
        unsigned mask0 = __ballot_sync(0xffffffffu, pk0);
        if (mask0) {
            int leader = __ffs(mask0) - 1;
            int wb = 0;
            if (lane == leader) wb = atomicAdd(s_cnt, __popc(mask0));
            wb = __shfl_sync(0xffffffffu, wb, leader);
            if (pk0) {
                int rank = __popc(mask0 & ((1u << lane) - 1u));
                keys[*s_base + wb + rank] = f2k(e0 * invN);
            }
        }
        unsigned mask1 = __ballot_sync(0xffffffffu, pk1);
        if (mask1) {
            int leader = __ffs(mask1) - 1;
            int wb = 0;
            if (lane == leader) wb = atomicAdd(s_cnt, __popc(mask1));
            wb = __shfl_sync(0xffffffffu, wb, leader);
            if (pk1) {
                int rank = __popc(mask1 & ((1u << lane) - 1u));
                keys[*s_base + wb + rank] = f2k(o0 * invN);
            }
        }
    }
    __syncthreads();
}

// ---------------- fused corr: 1 fwd 1024 FFT + spectral pooling + 3 half-size inverse FFTs ----------------
__global__ void corr_fused_kernel() {
    extern __shared__ float smem[];
    __shared__ double wsum[8], wsq[8];
    __shared__ int s_cnt, s_base;
    int ch = blockIdx.x;
    int b  = ch >> 9;
    float* zr = smem;
    float* zi = smem + ZSTR;
    float* wr = smem + 2 * ZSTR;
    float* wi = smem + 3 * ZSTR;
    float2* tws = (float2*)(smem + 4 * ZSTR);   // 512 entries, 4 KB
    int tid = threadIdx.x;

    {
        float4 t = ((const float4*)g_twid)[tid];
        ((float4*)tws)[tid] = t;
    }
    {
        float4 qa = ((const float4*)(g_qT + (size_t)ch * L_))[tid];
        float4 ka = ((const float4*)(g_kT + (size_t)ch * L_))[tid];
        int t0 = tid * 4;
        int r0 = IDX((int)(__brev((unsigned)(t0  )) >> 22));
        int r1 = IDX((int)(__brev((unsigned)(t0+1)) >> 22));
        int r2 = IDX((int)(__brev((unsigned)(t0+2)) >> 22));
        int r3 = IDX((int)(__brev((unsigned)(t0+3)) >> 22));
        zr[r0] = qa.x; zi[r0] = ka.x;
        zr[r1] = qa.y; zi[r1] = ka.y;
        zr[r2] = qa.z; zi[r2] = ka.z;
        zr[r3] = qa.w; zi[r3] = ka.w;
    }
    __syncthreads();

    fft_pairs(zr, zi, 1024, 10, tws, false, tid);   // packed forward FFT, natural order

    // scale 0: N=1024 -> 512-pt IFFT
    hermY(zr, zi, wr, wi, 1024, 9, 0, tws, tid);
    __syncthreads();
    fft_pairs(wr, wi, 512, 9, tws, true, tid);
    epilogue(0, ch, b, b, 1024, wr, wi, tid, wsum, wsq, &s_cnt, &s_base);

    // scale 1
    derive_half(zr, zi, 512, 0, tws, tid);
    __syncthreads();
    hermY(zr, zi, wr, wi, 512, 8, 1, tws, tid);
    __syncthreads();
    fft_pairs(wr, wi, 256, 8, tws, true, tid);
    epilogue(1, ch, b, 16 + b, 512, wr, wi, tid, wsum, wsq, &s_cnt, &s_base);

    // scale 2
    derive_half(zr, zi, 256, 1, tws, tid);
    __syncthreads();
    hermY(zr, zi, wr, wi, 256, 7, 2, tws, tid);
    __syncthreads();
    fft_pairs(wr, wi, 128, 7, tws, true, tid);
    epilogue(2, ch, b, 32 + b, 256, wr, wi, tid, wsum, wsq, &s_cnt, &s_base);
}

// ---------------- cm: 8-way channel-partial sums + combine ----------------
__global__ void cm_part_kernel() {
    int idx = blockIdx.x * blockDim.x + threadIdx.x;
    if (idx >= 8 * B_ * TOTL) return;
    int i    = idx % (B_ * TOTL);
    int part = idx / (B_ * TOTL);
    int sIdx, b, t, Ls;
    if (i < 16384)      { sIdx = 0; Ls = 1024; int j = i;         b = j >> 10; t = j & 1023; }
    else if (i < 24576) { sIdx = 1; Ls = 512;  int j = i - 16384; b = j >> 9;  t = j & 511;  }
    else                { sIdx = 2; Ls = 256;  int j = i - 24576; b = j >> 8;  t = j & 255;  }
    const float* base = g_corr + corrOff(sIdx) + (size_t)(b * CH + part * 64) * Ls + t;
    float a0 = 0.f, a1 = 0.f, a2 = 0.f, a3 = 0.f;
    #pragma unroll 4
    for (int ch = 0; ch < 64; ch += 4) {
        a0 += base[(size_t)ch * Ls];
        a1 += base[(size_t)(ch + 1) * Ls];
        a2 += base[(size_t)(ch + 2) * Ls];
        a3 += base[(size_t)(ch + 3) * Ls];
    }
    g_cmp[idx] = (a0 + a1) + (a2 + a3);
}

__global__ void cm_combine_kernel() {
    int i = blockIdx.x * blockDim.x + threadIdx.x;
    if (i >= B_ * TOTL) return;
    float s = 0.0f;
    #pragma unroll
    for (int p = 0; p < 8; p++) s += g_cmp[(size_t)p * (B_ * TOTL) + i];
    g_cm[i] = s;
}

// ---------------- fused hist+scan: pass 0 (12b, + MLP), pass 1 (12b), pass 2 (8b) ----------------
__global__ void histscan_kernel(int pass,
        const float* __restrict__ w1, const float* __restrict__ b1,
        const float* __restrict__ w2, const float* __restrict__ b2,
        const float* __restrict__ w3, const float* __restrict__ b3) {
    __shared__ unsigned hl[4096];
    __shared__ unsigned sscan[TPB];
    __shared__ int s_last, s_k;
    __shared__ int s_pkred[8];
    int seg = blockIdx.y;
    int sIdx = seg >> 4, b = seg & 15;
    int Ls = cLs[sIdx];
    int tid = threadIdx.x;
    int lane = tid & 31;
    unsigned* gh = g_h4k + (size_t)seg * 4096;
    unsigned* ctr = (pass == 0 ? g_done0 : (pass == 1 ? g_done1 : g_done2)) + seg;

    for (int i = tid; i < 4096; i += TPB) hl[i] = 0;
    __syncthreads();

    int cnt = g_pcount[seg];
    unsigned pref = (pass == 0) ? 0u : g_prefix[seg];
    const unsigned* keys = g_pkeys + corrOff(sIdx) + (size_t)b * CH * Ls;
    int stride = gridDim.x * TPB;
    int iters = (cnt + stride - 1) / stride;
    int i = blockIdx.x * TPB + tid;
    for (int it = 0; it < iters; it++, i += stride) {
        bool valid = (i < cnt);
        unsigned key = valid ? keys[i] : 0u;
        bool ok; unsigned bin;
        if (pass == 0)      { ok = valid;                                    bin = key >> 20; }
        else if (pass == 1) { ok = valid && ((key >> 20) == (pref >> 20));   bin = (key >> 8) & 0xfffu; }
        else                { ok = valid && ((key >> 8) == (pref >> 8));     bin = key & 0xffu; }
        unsigned tag = ok ? bin : 0xffffffffu;
        unsigned mm = __match_any_sync(0xffffffffu, tag);
        if (ok && lane == (__ffs(mm) - 1))
            atomicAdd(&hl[bin], (unsigned)__popc(mm));
    }
    __syncthreads();
    for (int j = tid; j < 4096; j += TPB)
        if (hl[j]) atomicAdd(&gh[j], hl[j]);
    __threadfence();
    if (tid == 0) {
        unsigned t = atomicAdd(ctr, 1u);
        s_last = (t == gridDim.x - 1) ? 1 : 0;
    }
    __syncthreads();
    if (!s_last) return;
    __threadfence();

    if (pass == 0) {
        const float* cm = g_cm + cCmSeg[sIdx] + b * Ls;
        int pcnt = 0;
        for (int t = tid + 1; t < Ls - 1; t += TPB) {
            float v = cm[t];
            if (v > cm[t - 1] && v > cm[t + 1]) pcnt++;
        }
        #pragma unroll
        for (int off = 16; off > 0; off >>= 1) pcnt += __shfl_down_sync(0xffffffffu, pcnt, off);
        if (lane == 0) s_pkred[tid >> 5] = pcnt;
        __syncthreads();
        if (tid == 0) {
            int pkc = 0;
            #pragma unroll
            for (int w = 0; w < 8; w++) pkc += s_pkred[w];
            const double invSC = 1.0 / SCST;
            float f2 = (float)pkc;
            long long tot = 0;
            for (int ii = 0; ii < B_; ii++) tot += g_sqll[sIdx * 16 + ii];
            float f0 = (float)((double)tot * invSC / ((double)B_ * (double)Ls));
            double n = (double)CH * (double)Ls;
            double s1 = (double)g_sumll[seg] * invSC;
            double s2 = (double)g_sqll[seg] * invSC;
            double mean = s1 / n;
            float f1 = (float)((s2 - mean * s1) / (n - 1.0));
            float h1[32];
            for (int j = 0; j < 32; j++) {
                float a = w1[j*3] * f0 + w1[j*3+1] * f1 + w1[j*3+2] * f2 + b1[j];
                h1[j] = a > 0.0f ? a : 0.0f;
            }
            float h2[16];
            for (int j = 0; j < 16; j++) {
                float a = b2[j];
                for (int i2 = 0; i2 < 32; i2++) a += w2[j*32+i2] * h1[i2];
                h2[j] = a > 0.0f ? a : 0.0f;
            }
            float a = b3[0];
            for (int i2 = 0; i2 < 16; i2++) a += w3[i2] * h2[i2];
            float ratio = 1.0f / (1.0f + expf(-a));
            int kv = (int)(ratio * (float)Ls);
            if (kv < 1) kv = 1;
            if (kv > Ls) kv = Ls;
            g_kvals[seg] = kv;
            s_k = kv;
        }
    } else {
        if (tid == 0) s_k = g_krem[seg];
    }
    __syncthreads();
    unsigned k = (unsigned)s_k;

    int nb = (pass == 2) ? 256 : 4096;
    int bpt = nb / TPB;
    int cstart = tid * bpt;
    unsigned myChunk = 0;
    for (int j = 0; j < bpt; j++) myChunk += gh[cstart + j];
    sscan[tid] = myChunk;
    __syncthreads();
    for (int off = 1; off < TPB; off <<= 1) {
        unsigned v = (tid + off < TPB) ? sscan[tid + off] : 0u;
        __syncthreads();
        sscan[tid] += v;
        __syncthreads();
    }
    unsigned incl = sscan[tid];
    unsigned cumBefore = incl - myChunk;
    if (myChunk > 0 && cumBefore < k && incl >= k) {
        unsigned cum = cumBefore;
        for (int bin = cstart + bpt - 1; bin >= cstart; --bin) {
            unsigned h = gh[bin];
            if (cum + h >= k) {
                if (pass == 0) {
                    g_prefix[seg] = (unsigned)bin << 20;
                    g_krem[seg] = (int)(k - cum);
                } else if (pass == 1) {
                    g_prefix[seg] = (pref & 0xfff00000u) | ((unsigned)bin << 8);
                    g_krem[seg] = (int)(k - cum);
                } else {
                    g_thresh[seg] = k2f((pref & 0xffffff00u) | (unsigned)bin);
                }
                break;
            }
            cum += h;
        }
    }
    __syncthreads();
    for (int j = tid; j < 4096; j += TPB) gh[j] = 0u;
    if (tid == 0) *ctr = 0u;
}

// ---------------- final: masked softmax * pooled v (pre-interp rows), shuffle reductions ----------------
__global__ void final_all_kernel(const float* __restrict__ swarr) {
    extern __shared__ float smem[];
    __shared__ float red8[8];
    __shared__ float s_m, s_inv;
    int sIdx = blockIdx.x >> 13;
    int ch   = blockIdx.x & (NCH - 1);
    int b    = ch >> 9;
    int seg  = sIdx * 16 + b;
    int Ls = cLs[sIdx];
    int tid = threadIdx.x;
    int lane = tid & 31, wid = tid >> 5;
    float* sc = smem;
    float* so = smem + Ls;

    const float4* c4 = (const float4*)(g_corr + corrOff(sIdx) + (size_t)ch * Ls);
    int nv = Ls >> 2;
    if (tid < nv) ((float4*)sc)[tid] = c4[tid];
    __syncthreads();

    float thr = g_thresh[seg];
    bool useAll = (g_pcount[seg] <= g_kvals[seg]);

    float m = 0.0f;
    for (int t = tid; t < Ls; t += TPB) {
        float a = 0.0f;
        if (t > 0 && t < Ls - 1) {
            float v = sc[t];
            if (v > sc[t - 1] && v > sc[t + 1] && (useAll || v >= thr)) a = v;
        }
        so[t] = a;
        m = fmaxf(m, a);
    }
    #pragma unroll
    for (int off = 16; off > 0; off >>= 1)
        m = fmaxf(m, __shfl_down_sync(0xffffffffu, m, off));
    if (lane == 0) red8[wid] = m;
    __syncthreads();
    if (tid == 0) {
        float mm = 0.0f;
        #pragma unroll
        for (int w = 0; w < 8; w++) mm = fmaxf(mm, red8[w]);
        s_m = mm;
    }
    __syncthreads();
    m = s_m;

    float ds = 0.0f;
    for (int t = tid; t < Ls; t += TPB) {
        float e = __expf(so[t] - m);
        so[t] = e;
        ds += e;
    }
    #pragma unroll
    for (int off = 16; off > 0; off >>= 1)
        ds += __shfl_down_sync(0xffffffffu, ds, off);
    if (lane == 0) red8[wid] = ds;
    __syncthreads();
    if (tid == 0) {
        float s = 0.0f;
        #pragma unroll
        for (int w = 0; w < 8; w++) s += red8[w];
        s_inv = 1.0f / s;
    }
    __syncthreads();
    float inv = s_inv;

    float sw = swarr[sIdx];
    float c = sw * inv;
    {
        float4 vv = ((const float4*)(g_vT + (size_t)ch * L_))[tid];
        if (sIdx == 0) {
            int t0 = tid * 4;
            so[t0  ] = c * so[t0  ] * vv.x;
            so[t0+1] = c * so[t0+1] * vv.y;
            so[t0+2] = c * so[t0+2] * vv.z;
            so[t0+3] = c * so[t0+3] * vv.w;
        } else if (sIdx == 1) {
            int t0 = tid * 2;
            so[t0  ] = c * so[t0  ] * ((vv.x + vv.y) * 0.5f);
            so[t0+1] = c * so[t0+1] * ((vv.z + vv.w) * 0.5f);
        } else {
            so[tid] = c * so[tid] * ((vv.x + vv.y + vv.z + vv.w) * 0.25f);
        }
    }
    __syncthreads();

    float* outRow = g_wv + corrOff(sIdx) + (size_t)ch * Ls;
    if (tid < nv) ((float4*)outRow)[tid] = ((const float4*)so)[tid];
}

// ---------------- untranspose + on-the-fly interpolation + sum 3 scales ----------------
__global__ void untranspose_kernel(float* __restrict__ out) {
    __shared__ float tile[32][33];
    int b   = blockIdx.z;
    int ch0 = blockIdx.x * 32;
    int l0  = blockIdx.y * 32;
    int tx = threadIdx.x, ty = threadIdx.y;
    int l = l0 + tx;

    float s1 = 0.5f * (float)l - 0.25f;  if (s1 < 0.0f) s1 = 0.0f;
    int x10 = (int)s1; int x11 = x10 + 1; if (x11 > 511) x11 = 511;
    float lam1 = s1 - (float)x10;
    float s2 = 0.25f * (float)l - 0.375f; if (s2 < 0.0f) s2 = 0.0f;
    int x20 = (int)s2; int x21 = x20 + 1; if (x21 > 255) x21 = 255;
    float lam2 = s2 - (float)x20;

    const float* w1base = g_wv + (size_t)NCH * 1024;
    const float* w2base = g_wv + (size_t)NCH * 1536;

    for (int r = ty; r < 32; r += 8) {
        size_t ch = (size_t)b * CH + ch0 + r;
        const float* w0 = g_wv + ch * 1024;
        const float* w1 = w1base + ch * 512;
        const float* w2 = w2base + ch * 256;
        float v = w0[l]
                + w1[x10] * (1.0f - lam1) + w1[x11] * lam1
                + w2[x20] * (1.0f - lam2) + w2[x21] * lam2;
        tile[r][tx] = v;
    }
    __syncthreads();
    for (int r = ty; r < 32; r += 8)
        out[((size_t)b * L_ + (l0 + r)) * CH + ch0 + tx] = tile[tx][r];
}

// ---------------- launch ----------------
extern "C" void kernel_launch(void* const* d_in, const int* in_sizes, int n_in,
                              void* d_out, int out_size) {
    (void)in_sizes; (void)n_in; (void)out_size;
    const float* q  = (const float*)d_in[0];
    const float* kk = (const float*)d_in[1];
    const float* v  = (const float*)d_in[2];
    const float* sw = (const float*)d_in[3];
    const float* w1 = (const float*)d_in[4];
    const float* b1 = (const float*)d_in[5];
    const float* w2 = (const float*)d_in[6];
    const float* b2 = (const float*)d_in[7];
    const float* w3 = (const float*)d_in[8];
    const float* b3 = (const float*)d_in[9];
    float* out = (float*)d_out;

    init_kernel<<<64, TPB>>>();

    dim3 tgrid(CH / 32, L_ / 32, B_);
    dim3 tblk(32, 8);
    transpose3_kernel<<<tgrid, tblk>>>(q, kk, v);

    int fftSmem = 4 * ZSTR * sizeof(float) + 512 * sizeof(float2);   // 20992 B
    corr_fused_kernel<<<NCH, TPB, fftSmem>>>();

    cm_part_kernel<<<(8 * B_ * TOTL + TPB - 1) / TPB, TPB>>>();
    cm_combine_kernel<<<(B_ * TOTL + TPB - 1) / TPB, TPB>>>();

    dim3 hg(32, NSEG);
    histscan_kernel<<<hg, TPB>>>(0, w1, b1, w2, b2, w3, b3);
    histscan_kernel<<<hg, TPB>>>(1, w1, b1, w2, b2, w3, b3);
    histscan_kernel<<<hg, TPB>>>(2, w1, b1, w2, b2, w3, b3);

    final_all_kernel<<<3 * NCH, TPB, 2 * 1024 * sizeof(float)>>>(sw);

    untranspose_kernel<<<tgrid, tblk>>>(out);
}